// round 8
// baseline (speedup 1.0000x reference)
#include <cuda_runtime.h>
#include <cuda_fp16.h>
#include <cstdint>
#include <cstddef>

// Problem: B=4, S=2048, H=1024, 3H=3072, rows = B*S = 8192.
#define B_ 4
#define S_ 2048
#define H_ 1024
#define H3_ 3072

// ---------------------------------------------------------------------------
// Scratch (__device__ globals; no allocation allowed).
// ---------------------------------------------------------------------------
__device__ __half g_xh  [(size_t)8192 * 1024];     // X fp16                  (16 MB)
__device__ __half g_wt  [(size_t)3072 * 1024];     // W^T fp16 [3H][H]        ( 6 MB)
__device__ __half g_qkvh[(size_t)8192 * 3072];     // QKV fp16 [rows][3H]     (48 MB)
__device__ float  g_sc  [(size_t)4 * 2048 * 2048]; // scores fp32             (64 MB)
__device__ __half g_p   [(size_t)4 * 2048 * 2048]; // probs fp16              (32 MB)
__device__ __half g_vt  [(size_t)4 * 1024 * 2048]; // V^T fp16 [b][d][s]      (16 MB)

__device__ __forceinline__ uint32_t smem_to_u32(const void* p) {
    uint32_t a;
    asm("{ .reg .u64 t; cvta.to.shared.u64 t, %1; cvt.u32.u64 %0, t; }" : "=r"(a) : "l"(p));
    return a;
}

// SW128 swizzle on 128-byte rows: bits[6:4] ^= bits[9:7].
#define SW128(o) ((o) ^ ((((uint32_t)(o)) >> 3) & 0x70))

__device__ __forceinline__ void ldsm_x4(uint32_t (&r)[4], uint32_t addr) {
    asm volatile("ldmatrix.sync.aligned.m8n8.x4.shared.b16 {%0,%1,%2,%3}, [%4];"
        : "=r"(r[0]), "=r"(r[1]), "=r"(r[2]), "=r"(r[3]) : "r"(addr));
}
__device__ __forceinline__ void mma16816(float (&d)[4], const uint32_t (&a)[4],
                                         uint32_t b0, uint32_t b1) {
    asm volatile("mma.sync.aligned.m16n8k16.row.col.f32.f16.f16.f32 "
        "{%0,%1,%2,%3},{%4,%5,%6,%7},{%8,%9},{%0,%1,%2,%3};"
        : "+f"(d[0]), "+f"(d[1]), "+f"(d[2]), "+f"(d[3])
        : "r"(a[0]), "r"(a[1]), "r"(a[2]), "r"(a[3]), "r"(b0), "r"(b1));
}

// ---------------------------------------------------------------------------
// fp16 GEMM:  C[M,N] = alpha * A[M,K] * B[N,K]^T (+bias)
//   CTA tile 128x128, 128 threads = 4 warps (2x2), warp tile 64x64.
//   BK=64 (128B rows, SW128), 3-stage cp.async pipeline.
//   __launch_bounds__(128, 2): 2 CTAs/SM so barriers of one CTA are covered
//   by the other (round-7 regression root cause was 1 CTA/SM).
//   Crossbar per CTA k-tile: 64KB vs 1M MACs = 16 MAC/B.
//   EPI=0: fp16 out + bias.  EPI=1: fp32 out * alpha.  blockIdx.z = batch.
// Smem: A stages 16KB x3 at 0; B stages 16KB x3 at 49152. Total 98304.
// ---------------------------------------------------------------------------
#define BM 128
#define BN 128
#define BK 64
static constexpr int A_STAGE = 16384;
static constexpr int B_STAGE = 16384;
static constexpr int B_BASE  = 3 * A_STAGE;                // 49152
static constexpr int GEMM_SMEM = 3 * (A_STAGE + B_STAGE);  // 98304

template <int EPI>
__global__ void __launch_bounds__(128, 2) gemm_f16(
    const __half* __restrict__ A, const __half* __restrict__ Bm, void* __restrict__ Cv,
    const float* __restrict__ bias,
    int lda, int ldb, int ldc, int K,
    long long sA, long long sB, long long sC, float alpha)
{
    extern __shared__ char smem[];
    const uint32_t su = smem_to_u32(smem);
    const int tid = threadIdx.x, warp = tid >> 5, lane = tid & 31;
    const int bz = blockIdx.z;
    A  += (size_t)bz * sA;
    Bm += (size_t)bz * sB;
    const int cN = blockIdx.x * BN;
    const int cM = blockIdx.y * BM;
    const int wm = (warp >> 1) * 64;   // 2 warp-rows
    const int wn = (warp & 1) * 64;    // 2 warp-cols

    // cp.async geometry: 128 threads, one 128B row per thread, 8 x 16B chunks.
    const __half* ga = A  + (size_t)(cM + tid) * lda;
    const __half* gb = Bm + (size_t)(cN + tid) * ldb;

    auto loadtile = [&](int p, int kt) {
        const int k0 = kt * BK;
        const uint32_t ab = su + p * A_STAGE;
        const uint32_t bb = su + B_BASE + p * B_STAGE;
#pragma unroll
        for (int c = 0; c < 8; c++) {
            const uint32_t off = SW128(tid * 128 + c * 16);
            asm volatile("cp.async.cg.shared.global [%0], [%1], 16;"
                :: "r"(ab + off), "l"(ga + k0 + c * 8) : "memory");
            asm volatile("cp.async.cg.shared.global [%0], [%1], 16;"
                :: "r"(bb + off), "l"(gb + k0 + c * 8) : "memory");
        }
        asm volatile("cp.async.commit_group;" ::: "memory");
    };

    float acc[4][8][4] = {};
    const int nk = K / BK;
    loadtile(0, 0);
    if (nk > 1) loadtile(1, 1);
    if (nk > 2) loadtile(2, 2);

    // ldmatrix lane geometry (element units).
    const int a_row = lane & 15;
    const int a_k   = (lane >> 4) * 8;
    const int b_n   = ((lane >> 4) * 8) + (lane & 7);
    const int b_k   = ((lane >> 3) & 1) * 8;

    for (int kt = 0; kt < nk; kt++) {
        const int rem = nk - kt - 1;
        if (rem >= 2)      asm volatile("cp.async.wait_group 2;" ::: "memory");
        else if (rem == 1) asm volatile("cp.async.wait_group 1;" ::: "memory");
        else               asm volatile("cp.async.wait_group 0;" ::: "memory");
        __syncthreads();
        const int p = kt % 3;
        const uint32_t ab = su + p * A_STAGE;
        const uint32_t bb = su + B_BASE + p * B_STAGE;
#pragma unroll
        for (int ks = 0; ks < 4; ks++) {
            const int kb = ks * 16;
            uint32_t af[4][4];
#pragma unroll
            for (int mt = 0; mt < 4; mt++) {
                const int r = wm + mt * 16 + a_row;
                ldsm_x4(af[mt], ab + SW128(r * 128 + (kb + a_k) * 2));
            }
#pragma unroll
            for (int j = 0; j < 4; j++) {       // 4 x n16 groups = 64 cols
                uint32_t bf[4];
                const int n = wn + j * 16 + b_n;
                ldsm_x4(bf, bb + SW128(n * 128 + (kb + b_k) * 2));
#pragma unroll
                for (int mt = 0; mt < 4; mt++) {
                    mma16816(acc[mt][j * 2],     af[mt], bf[0], bf[1]);
                    mma16816(acc[mt][j * 2 + 1], af[mt], bf[2], bf[3]);
                }
            }
        }
        __syncthreads();
        if (kt + 3 < nk) loadtile(p, kt + 3);
    }

    // Epilogue. thread: rows (lane/4, +8), cols 2*(lane%4)+{0,1} of each 16x8 tile.
    const int er = lane >> 2;
    const int ec = (lane & 3) * 2;
#pragma unroll
    for (int mt = 0; mt < 4; mt++) {
#pragma unroll
        for (int nt = 0; nt < 8; nt++) {
            const int r0  = cM + wm + mt * 16 + er;
            const int col = cN + wn + nt * 8 + ec;
            if (EPI == 0) {
                __half* C = (__half*)Cv + (size_t)bz * sC + (size_t)r0 * ldc + col;
                const float b0 = bias[col], b1 = bias[col + 1];
                *(__half2*)C = __floats2half2_rn(acc[mt][nt][0] + b0, acc[mt][nt][1] + b1);
                *(__half2*)(C + (size_t)8 * ldc) =
                    __floats2half2_rn(acc[mt][nt][2] + b0, acc[mt][nt][3] + b1);
            } else {
                float* C = (float*)Cv + (size_t)bz * sC + (size_t)r0 * ldc + col;
                *(float2*)C = make_float2(acc[mt][nt][0] * alpha, acc[mt][nt][1] * alpha);
                *(float2*)(C + (size_t)8 * ldc) =
                    make_float2(acc[mt][nt][2] * alpha, acc[mt][nt][3] * alpha);
            }
        }
    }
}

// ---------------------------------------------------------------------------
// fp32 -> fp16 elementwise convert (8 elems / thread)
// ---------------------------------------------------------------------------
__global__ void __launch_bounds__(256) convert_f2h(const float* __restrict__ in,
                                                   __half* __restrict__ out)
{
    const size_t i = ((size_t)blockIdx.x * 256 + threadIdx.x) * 8;
    const float4 a = *(const float4*)(in + i);
    const float4 b = *(const float4*)(in + i + 4);
    __half2 h[4];
    h[0] = __floats2half2_rn(a.x, a.y);
    h[1] = __floats2half2_rn(a.z, a.w);
    h[2] = __floats2half2_rn(b.x, b.y);
    h[3] = __floats2half2_rn(b.z, b.w);
    *(uint4*)(out + i) = *(uint4*)h;
}

// W [H][3H] fp32 -> Wt [3H][H] fp16
__global__ void __launch_bounds__(256) transpose_w(const float* __restrict__ W,
                                                   __half* __restrict__ Wt)
{
    __shared__ float tile[32][33];
    const int n0 = blockIdx.x * 32;
    const int k0 = blockIdx.y * 32;
    const int tx = threadIdx.x & 31, ty = threadIdx.x >> 5;
#pragma unroll
    for (int j = 0; j < 4; j++)
        tile[ty + 8 * j][tx] = W[(size_t)(k0 + ty + 8 * j) * H3_ + n0 + tx];
    __syncthreads();
#pragma unroll
    for (int j = 0; j < 4; j++)
        Wt[(size_t)(n0 + ty + 8 * j) * H_ + k0 + tx] = __float2half_rn(tile[tx][ty + 8 * j]);
}

// V slice of QKVh [8192][3072] (cols 2048..3071) -> Vt [b][d][s] fp16
__global__ void __launch_bounds__(256) transpose_v(const __half* __restrict__ qkvh,
                                                   __half* __restrict__ vt)
{
    __shared__ __half tile[32][34];
    const int b  = blockIdx.z;
    const int s0 = blockIdx.x * 32;
    const int d0 = blockIdx.y * 32;
    const int tx = threadIdx.x & 31, ty = threadIdx.x >> 5;
#pragma unroll
    for (int j = 0; j < 4; j++)
        tile[ty + 8 * j][tx] =
            qkvh[((size_t)b * S_ + s0 + ty + 8 * j) * H3_ + 2 * H_ + d0 + tx];
    __syncthreads();
#pragma unroll
    for (int j = 0; j < 4; j++)
        vt[((size_t)b * H_ + d0 + ty + 8 * j) * S_ + s0 + tx] = tile[tx][ty + 8 * j];
}

// ---------------------------------------------------------------------------
// Masked softmax: fp32 scores row -> fp16 probs row. mask != 0 => weight 0.
// ---------------------------------------------------------------------------
__global__ void __launch_bounds__(256) softmax_mask_kernel(const float* __restrict__ sc,
                                                           __half* __restrict__ pout,
                                                           const int* __restrict__ mask)
{
    const int b = blockIdx.y;
    const int q = blockIdx.x;
    const float* row = sc + ((size_t)b * S_ + q) * S_;
    __half* prow = pout + ((size_t)b * S_ + q) * S_;
    const int* mrow = mask + (size_t)b * S_;

    const int tid = threadIdx.x, lane = tid & 31, warp = tid >> 5;
    float v[8];
    int mk[8];
    float mx = -3.4e38f;
#pragma unroll
    for (int i = 0; i < 8; i++) {
        const int k = tid + i * 256;
        v[i] = row[k];
        mk[i] = mrow[k];
        if (!mk[i]) mx = fmaxf(mx, v[i]);
    }
    __shared__ float rmax[8], rsum[8];
#pragma unroll
    for (int o = 16; o > 0; o >>= 1) mx = fmaxf(mx, __shfl_xor_sync(0xffffffffu, mx, o));
    if (lane == 0) rmax[warp] = mx;
    __syncthreads();
    float bmax = rmax[0];
#pragma unroll
    for (int w = 1; w < 8; w++) bmax = fmaxf(bmax, rmax[w]);
    float s = 0.f;
#pragma unroll
    for (int i = 0; i < 8; i++) {
        const float e = mk[i] ? 0.f : expf(v[i] - bmax);
        v[i] = e;
        s += e;
    }
#pragma unroll
    for (int o = 16; o > 0; o >>= 1) s += __shfl_xor_sync(0xffffffffu, s, o);
    if (lane == 0) rsum[warp] = s;
    __syncthreads();
    float bsum = 0.f;
#pragma unroll
    for (int w = 0; w < 8; w++) bsum += rsum[w];
    const float inv = (bsum > 0.f) ? (1.f / bsum) : 0.f;
#pragma unroll
    for (int i = 0; i < 8; i++) prow[tid + i * 256] = __float2half_rn(v[i] * inv);
}

// ---------------------------------------------------------------------------
// Launch
// ---------------------------------------------------------------------------
extern "C" void kernel_launch(void* const* d_in, const int* in_sizes, int n_in,
                              void* d_out, int out_size)
{
    const float* X    = (const float*)d_in[0];
    const int*   mask = (const int*)  d_in[1];
    const float* W    = (const float*)d_in[2];
    const float* bias = (const float*)d_in[3];
    float*       out  = (float*)d_out;

    __half *xh, *wt, *qkvh, *p, *vt;
    float* sc;
    cudaGetSymbolAddress((void**)&xh,   g_xh);
    cudaGetSymbolAddress((void**)&wt,   g_wt);
    cudaGetSymbolAddress((void**)&qkvh, g_qkvh);
    cudaGetSymbolAddress((void**)&sc,   g_sc);
    cudaGetSymbolAddress((void**)&p,    g_p);
    cudaGetSymbolAddress((void**)&vt,   g_vt);

    cudaFuncSetAttribute(gemm_f16<0>, cudaFuncAttributeMaxDynamicSharedMemorySize, GEMM_SMEM);
    cudaFuncSetAttribute(gemm_f16<1>, cudaFuncAttributeMaxDynamicSharedMemorySize, GEMM_SMEM);

    // 0) convert X -> fp16; transpose W -> Wt fp16
    convert_f2h<<<(size_t)8192 * 1024 / (256 * 8), 256>>>(X, xh);
    transpose_w<<<dim3(H3_ / 32, H_ / 32), 256>>>(W, wt);

    // 1) QKVh = Xh @ Wt^T + b   (M=8192, N=3072, K=1024) -> fp16
    gemm_f16<0><<<dim3(H3_ / BN, 8192 / BM, 1), 128, GEMM_SMEM>>>(
        xh, wt, qkvh, bias, H_, H_, H3_, H_, 0LL, 0LL, 0LL, 1.0f);

    // 2) scores = (Q @ K^T) / 32  per batch -> fp32
    gemm_f16<1><<<dim3(S_ / BN, S_ / BM, B_), 128, GEMM_SMEM>>>(
        qkvh, qkvh + H_, sc, nullptr, H3_, H3_, S_, H_,
        (long long)S_ * H3_, (long long)S_ * H3_, (long long)S_ * S_, 0.03125f);

    // 3) masked softmax: fp32 scores -> fp16 P
    softmax_mask_kernel<<<dim3(S_, B_), 256>>>(sc, p, mask);

    // 3b) transpose V -> Vt [b][d][s]
    transpose_v<<<dim3(S_ / 32, H_ / 32, B_), 256>>>(qkvh, vt);

    // 4) out = P @ Vt^T  per batch (M=2048, N=1024, K=2048) -> fp32
    gemm_f16<1><<<dim3(H_ / BN, S_ / BM, B_), 128, GEMM_SMEM>>>(
        p, vt, out, nullptr, S_, S_, H_, S_,
        (long long)S_ * S_, (long long)S_ * H_, (long long)S_ * H_, 1.0f);
}

// round 9
// speedup vs baseline: 1.4958x; 1.4958x over previous
#include <cuda_runtime.h>
#include <cuda_fp16.h>
#include <cstdint>
#include <cstddef>

// Problem: B=4, S=2048, H=1024, 3H=3072, rows = B*S = 8192.
#define B_ 4
#define S_ 2048
#define H_ 1024
#define H3_ 3072

// ---------------------------------------------------------------------------
// Scratch (__device__ globals; no allocation allowed).
// ---------------------------------------------------------------------------
__device__ __half g_xh  [(size_t)8192 * 1024];     // X fp16                  (16 MB)
__device__ __half g_wt  [(size_t)3072 * 1024];     // W^T fp16 [3H][H]        ( 6 MB)
__device__ __half g_qkvh[(size_t)8192 * 3072];     // QKV fp16 [rows][3H]     (48 MB)
__device__ float  g_sc  [(size_t)4 * 2048 * 2048]; // scores fp32             (64 MB)
__device__ __half g_p   [(size_t)4 * 2048 * 2048]; // probs fp16              (32 MB)
__device__ __half g_vt  [(size_t)4 * 1024 * 2048]; // V^T fp16 [b][d][s]      (16 MB)

__device__ __forceinline__ uint32_t smem_to_u32(const void* p) {
    uint32_t a;
    asm("{ .reg .u64 t; cvta.to.shared.u64 t, %1; cvt.u32.u64 %0, t; }" : "=r"(a) : "l"(p));
    return a;
}

// SW128 swizzle on 128-byte rows: bits[6:4] ^= bits[9:7].
#define SW128(o) ((o) ^ ((((uint32_t)(o)) >> 3) & 0x70))

__device__ __forceinline__ void ldsm_x4(uint32_t (&r)[4], uint32_t addr) {
    asm volatile("ldmatrix.sync.aligned.m8n8.x4.shared.b16 {%0,%1,%2,%3}, [%4];"
        : "=r"(r[0]), "=r"(r[1]), "=r"(r[2]), "=r"(r[3]) : "r"(addr));
}
__device__ __forceinline__ void mma16816(float (&d)[4], const uint32_t (&a)[4],
                                         uint32_t b0, uint32_t b1) {
    asm volatile("mma.sync.aligned.m16n8k16.row.col.f32.f16.f16.f32 "
        "{%0,%1,%2,%3},{%4,%5,%6,%7},{%8,%9},{%0,%1,%2,%3};"
        : "+f"(d[0]), "+f"(d[1]), "+f"(d[2]), "+f"(d[3])
        : "r"(a[0]), "r"(a[1]), "r"(a[2]), "r"(a[3]), "r"(b0), "r"(b1));
}

// ---------------------------------------------------------------------------
// fp16 GEMM:  C[M,N] = alpha * A[M,K] * B[N,K]^T (+bias)
//   ROUND-4 geometry (proven 16 warps/SM): CTA 128x128, 256 thr = 8 warps
//   (2x4), warp tile 64x32, BK=64 (128B rows, SW128), regs ~124 -> 2 CTA/SM.
//   NEW vs round 4: 3-stage cp.async pipeline + ONE __syncthreads per k-iter
//   (cutlass multistage order: wait -> sync -> issue kt+2 -> compute kt).
//   EPI=0: fp16 out + bias.  EPI=1: fp32 out * alpha.  blockIdx.z = batch.
// Smem: A stages 16KB x3 at 0; B stages 16KB x3 at 49152. Total 98304/CTA.
// ---------------------------------------------------------------------------
#define BM 128
#define BN 128
#define BK 64
static constexpr int A_STAGE = 16384;
static constexpr int B_STAGE = 16384;
static constexpr int B_BASE  = 3 * A_STAGE;                // 49152
static constexpr int GEMM_SMEM = 3 * (A_STAGE + B_STAGE);  // 98304

template <int EPI>
__global__ void __launch_bounds__(256, 2) gemm_f16(
    const __half* __restrict__ A, const __half* __restrict__ Bm, void* __restrict__ Cv,
    const float* __restrict__ bias,
    int lda, int ldb, int ldc, int K,
    long long sA, long long sB, long long sC, float alpha)
{
    extern __shared__ char smem[];
    const uint32_t su = smem_to_u32(smem);
    const int tid = threadIdx.x, warp = tid >> 5, lane = tid & 31;
    const int bz = blockIdx.z;
    A  += (size_t)bz * sA;
    Bm += (size_t)bz * sB;
    const int cN = blockIdx.x * BN;
    const int cM = blockIdx.y * BM;
    const int wm = (warp >> 2) * 64;   // 2 warp-rows
    const int wn = (warp & 3) * 32;    // 4 warp-cols

    // cp.async geometry: 2 threads per 128B row, 4 x 16B chunks each.
    const int row = tid >> 1;
    const int cb  = (tid & 1) * 4;
    const __half* ga = A  + (size_t)(cM + row) * lda;
    const __half* gb = Bm + (size_t)(cN + row) * ldb;

    auto loadtile = [&](int p, int kt) {
        const int k0 = kt * BK;
        const uint32_t ab = su + p * A_STAGE;
        const uint32_t bb = su + B_BASE + p * B_STAGE;
#pragma unroll
        for (int c = 0; c < 4; c++) {
            const uint32_t off = SW128(row * 128 + (cb + c) * 16);
            asm volatile("cp.async.cg.shared.global [%0], [%1], 16;"
                :: "r"(ab + off), "l"(ga + k0 + (cb + c) * 8) : "memory");
            asm volatile("cp.async.cg.shared.global [%0], [%1], 16;"
                :: "r"(bb + off), "l"(gb + k0 + (cb + c) * 8) : "memory");
        }
        asm volatile("cp.async.commit_group;" ::: "memory");
    };

    float acc[4][4][4] = {};
    const int nk = K / BK;
    loadtile(0, 0);
    if (nk > 1) loadtile(1, 1);

    // ldmatrix lane geometry (element units).
    const int a_row = lane & 15;
    const int a_k   = (lane >> 4) * 8;
    const int b_n   = ((lane >> 4) * 8) + (lane & 7);
    const int b_k   = ((lane >> 3) & 1) * 8;

    for (int kt = 0; kt < nk; kt++) {
        // Ensure stage kt is resident. Outstanding groups beyond kt: at most 1.
        if (kt + 1 < nk) asm volatile("cp.async.wait_group 1;" ::: "memory");
        else             asm volatile("cp.async.wait_group 0;" ::: "memory");
        __syncthreads();
        // Slot (kt+2)%3 held stage kt-1; all warps finished it before this
        // barrier, so it is free to refill now (overlaps compute below).
        if (kt + 2 < nk) loadtile((kt + 2) % 3, kt + 2);

        const int p = kt % 3;
        const uint32_t ab = su + p * A_STAGE;
        const uint32_t bb = su + B_BASE + p * B_STAGE;
#pragma unroll
        for (int ks = 0; ks < 4; ks++) {
            const int kb = ks * 16;
            uint32_t af[4][4];
#pragma unroll
            for (int mt = 0; mt < 4; mt++) {
                const int r = wm + mt * 16 + a_row;
                ldsm_x4(af[mt], ab + SW128(r * 128 + (kb + a_k) * 2));
            }
#pragma unroll
            for (int np = 0; np < 2; np++) {
                uint32_t bf[4];
                const int n = wn + np * 16 + b_n;
                ldsm_x4(bf, bb + SW128(n * 128 + (kb + b_k) * 2));
#pragma unroll
                for (int mt = 0; mt < 4; mt++) {
                    mma16816(acc[mt][np * 2],     af[mt], bf[0], bf[1]);
                    mma16816(acc[mt][np * 2 + 1], af[mt], bf[2], bf[3]);
                }
            }
        }
        // No second barrier: next iteration's wait+sync provides the ordering.
    }

    // Epilogue. thread: rows (lane/4, +8), cols 2*(lane%4)+{0,1} of each 16x8 tile.
    const int er = lane >> 2;
    const int ec = (lane & 3) * 2;
#pragma unroll
    for (int mt = 0; mt < 4; mt++) {
#pragma unroll
        for (int nt = 0; nt < 4; nt++) {
            const int r0  = cM + wm + mt * 16 + er;
            const int col = cN + wn + nt * 8 + ec;
            if (EPI == 0) {
                __half* C = (__half*)Cv + (size_t)bz * sC + (size_t)r0 * ldc + col;
                const float b0 = bias[col], b1 = bias[col + 1];
                *(__half2*)C = __floats2half2_rn(acc[mt][nt][0] + b0, acc[mt][nt][1] + b1);
                *(__half2*)(C + (size_t)8 * ldc) =
                    __floats2half2_rn(acc[mt][nt][2] + b0, acc[mt][nt][3] + b1);
            } else {
                float* C = (float*)Cv + (size_t)bz * sC + (size_t)r0 * ldc + col;
                *(float2*)C = make_float2(acc[mt][nt][0] * alpha, acc[mt][nt][1] * alpha);
                *(float2*)(C + (size_t)8 * ldc) =
                    make_float2(acc[mt][nt][2] * alpha, acc[mt][nt][3] * alpha);
            }
        }
    }
}

// ---------------------------------------------------------------------------
// fp32 -> fp16 elementwise convert (8 elems / thread)
// ---------------------------------------------------------------------------
__global__ void __launch_bounds__(256) convert_f2h(const float* __restrict__ in,
                                                   __half* __restrict__ out)
{
    const size_t i = ((size_t)blockIdx.x * 256 + threadIdx.x) * 8;
    const float4 a = *(const float4*)(in + i);
    const float4 b = *(const float4*)(in + i + 4);
    __half2 h[4];
    h[0] = __floats2half2_rn(a.x, a.y);
    h[1] = __floats2half2_rn(a.z, a.w);
    h[2] = __floats2half2_rn(b.x, b.y);
    h[3] = __floats2half2_rn(b.z, b.w);
    *(uint4*)(out + i) = *(uint4*)h;
}

// W [H][3H] fp32 -> Wt [3H][H] fp16
__global__ void __launch_bounds__(256) transpose_w(const float* __restrict__ W,
                                                   __half* __restrict__ Wt)
{
    __shared__ float tile[32][33];
    const int n0 = blockIdx.x * 32;
    const int k0 = blockIdx.y * 32;
    const int tx = threadIdx.x & 31, ty = threadIdx.x >> 5;
#pragma unroll
    for (int j = 0; j < 4; j++)
        tile[ty + 8 * j][tx] = W[(size_t)(k0 + ty + 8 * j) * H3_ + n0 + tx];
    __syncthreads();
#pragma unroll
    for (int j = 0; j < 4; j++)
        Wt[(size_t)(n0 + ty + 8 * j) * H_ + k0 + tx] = __float2half_rn(tile[tx][ty + 8 * j]);
}

// V slice of QKVh [8192][3072] (cols 2048..3071) -> Vt [b][d][s] fp16
__global__ void __launch_bounds__(256) transpose_v(const __half* __restrict__ qkvh,
                                                   __half* __restrict__ vt)
{
    __shared__ __half tile[32][34];
    const int b  = blockIdx.z;
    const int s0 = blockIdx.x * 32;
    const int d0 = blockIdx.y * 32;
    const int tx = threadIdx.x & 31, ty = threadIdx.x >> 5;
#pragma unroll
    for (int j = 0; j < 4; j++)
        tile[ty + 8 * j][tx] =
            qkvh[((size_t)b * S_ + s0 + ty + 8 * j) * H3_ + 2 * H_ + d0 + tx];
    __syncthreads();
#pragma unroll
    for (int j = 0; j < 4; j++)
        vt[((size_t)b * H_ + d0 + ty + 8 * j) * S_ + s0 + tx] = tile[tx][ty + 8 * j];
}

// ---------------------------------------------------------------------------
// Masked softmax: fp32 scores row -> fp16 probs row. mask != 0 => weight 0.
// ---------------------------------------------------------------------------
__global__ void __launch_bounds__(256) softmax_mask_kernel(const float* __restrict__ sc,
                                                           __half* __restrict__ pout,
                                                           const int* __restrict__ mask)
{
    const int b = blockIdx.y;
    const int q = blockIdx.x;
    const float* row = sc + ((size_t)b * S_ + q) * S_;
    __half* prow = pout + ((size_t)b * S_ + q) * S_;
    const int* mrow = mask + (size_t)b * S_;

    const int tid = threadIdx.x, lane = tid & 31, warp = tid >> 5;
    float v[8];
    int mk[8];
    float mx = -3.4e38f;
#pragma unroll
    for (int i = 0; i < 8; i++) {
        const int k = tid + i * 256;
        v[i] = row[k];
        mk[i] = mrow[k];
        if (!mk[i]) mx = fmaxf(mx, v[i]);
    }
    __shared__ float rmax[8], rsum[8];
#pragma unroll
    for (int o = 16; o > 0; o >>= 1) mx = fmaxf(mx, __shfl_xor_sync(0xffffffffu, mx, o));
    if (lane == 0) rmax[warp] = mx;
    __syncthreads();
    float bmax = rmax[0];
#pragma unroll
    for (int w = 1; w < 8; w++) bmax = fmaxf(bmax, rmax[w]);
    float s = 0.f;
#pragma unroll
    for (int i = 0; i < 8; i++) {
        const float e = mk[i] ? 0.f : expf(v[i] - bmax);
        v[i] = e;
        s += e;
    }
#pragma unroll
    for (int o = 16; o > 0; o >>= 1) s += __shfl_xor_sync(0xffffffffu, s, o);
    if (lane == 0) rsum[warp] = s;
    __syncthreads();
    float bsum = 0.f;
#pragma unroll
    for (int w = 0; w < 8; w++) bsum += rsum[w];
    const float inv = (bsum > 0.f) ? (1.f / bsum) : 0.f;
#pragma unroll
    for (int i = 0; i < 8; i++) prow[tid + i * 256] = __float2half_rn(v[i] * inv);
}

// ---------------------------------------------------------------------------
// Launch
// ---------------------------------------------------------------------------
extern "C" void kernel_launch(void* const* d_in, const int* in_sizes, int n_in,
                              void* d_out, int out_size)
{
    const float* X    = (const float*)d_in[0];
    const int*   mask = (const int*)  d_in[1];
    const float* W    = (const float*)d_in[2];
    const float* bias = (const float*)d_in[3];
    float*       out  = (float*)d_out;

    __half *xh, *wt, *qkvh, *p, *vt;
    float* sc;
    cudaGetSymbolAddress((void**)&xh,   g_xh);
    cudaGetSymbolAddress((void**)&wt,   g_wt);
    cudaGetSymbolAddress((void**)&qkvh, g_qkvh);
    cudaGetSymbolAddress((void**)&sc,   g_sc);
    cudaGetSymbolAddress((void**)&p,    g_p);
    cudaGetSymbolAddress((void**)&vt,   g_vt);

    cudaFuncSetAttribute(gemm_f16<0>, cudaFuncAttributeMaxDynamicSharedMemorySize, GEMM_SMEM);
    cudaFuncSetAttribute(gemm_f16<1>, cudaFuncAttributeMaxDynamicSharedMemorySize, GEMM_SMEM);

    // 0) convert X -> fp16; transpose W -> Wt fp16
    convert_f2h<<<(size_t)8192 * 1024 / (256 * 8), 256>>>(X, xh);
    transpose_w<<<dim3(H3_ / 32, H_ / 32), 256>>>(W, wt);

    // 1) QKVh = Xh @ Wt^T + b   (M=8192, N=3072, K=1024) -> fp16
    gemm_f16<0><<<dim3(H3_ / BN, 8192 / BM, 1), 256, GEMM_SMEM>>>(
        xh, wt, qkvh, bias, H_, H_, H3_, H_, 0LL, 0LL, 0LL, 1.0f);

    // 2) scores = (Q @ K^T) / 32  per batch -> fp32
    gemm_f16<1><<<dim3(S_ / BN, S_ / BM, B_), 256, GEMM_SMEM>>>(
        qkvh, qkvh + H_, sc, nullptr, H3_, H3_, S_, H_,
        (long long)S_ * H3_, (long long)S_ * H3_, (long long)S_ * S_, 0.03125f);

    // 3) masked softmax: fp32 scores -> fp16 P
    softmax_mask_kernel<<<dim3(S_, B_), 256>>>(sc, p, mask);

    // 3b) transpose V -> Vt [b][d][s]
    transpose_v<<<dim3(S_ / 32, H_ / 32, B_), 256>>>(qkvh, vt);

    // 4) out = P @ Vt^T  per batch (M=2048, N=1024, K=2048) -> fp32
    gemm_f16<1><<<dim3(H_ / BN, S_ / BM, B_), 256, GEMM_SMEM>>>(
        p, vt, out, nullptr, S_, S_, H_, S_,
        (long long)S_ * S_, (long long)S_ * H_, (long long)S_ * H_, 1.0f);
}